// round 6
// baseline (speedup 1.0000x reference)
#include <cuda_runtime.h>

// Problem constants (fixed by the dataset)
#define NN   100000
#define EE   3200000
#define INF_ 128
#define HID_ 16
#define NC_  64

// ---------------- scratch (static device allocations only) ----------------
__device__ int   g_is64;
__device__ int   g_cnt[NN];
__device__ int   g_off[NN + 1];
__device__ int   g_cur[NN];
__device__ float g_dinv[NN];
__device__ int   g_rows[EE];            // CSR-by-destination source list
__device__ float g_h1s[NN * HID_];      // (x@W1) * dinv
__device__ float g_o1 [NN * HID_];      // relu layer-1 output
__device__ float g_h2s[NN * NC_];       // (o1@W2) * dinv
__device__ float g_Sacc[NC_ * 64];      // pooled colsum, 256B stride to spread L2 atomics
__device__ int   g_bsum[128];

// read edge value i (element index in the logical int array of length 2*E)
__device__ __forceinline__ int edge_at(const void* ei, int i) {
    if (g_is64) return (int)((const long long*)ei)[i];
    return ((const int*)ei)[i];
}

// ---------------- kernels ----------------

// Detect int64 vs int32 layout: as int32 words, int64 data (values < 2^31)
// has every odd word == 0. 64 consecutive zeros is conclusive.
__global__ void k_detect(const unsigned int* __restrict__ ei) {
    if (threadIdx.x == 0) {
        int all0 = 1;
        for (int i = 0; i < 64; i++)
            if (ei[2 * i + 1] != 0u) { all0 = 0; break; }
        g_is64 = all0;
    }
}

__global__ void k_init(int n) {
    int i = blockIdx.x * blockDim.x + threadIdx.x;
    if (i < n) g_cnt[i] = 0;
    if (i < NC_ * 64) g_Sacc[i] = 0.f;
}

__global__ void k_count(const void* __restrict__ ei, int e, int n) {
    int i = blockIdx.x * blockDim.x + threadIdx.x;
    if (i < e) {
        int c = edge_at(ei, e + i);          // col[i]
        if ((unsigned)c < (unsigned)n) atomicAdd(&g_cnt[c], 1);
    }
}

__global__ void k_scan_a(int n) {
    __shared__ int sm[1024];
    int t = threadIdx.x;
    int i = blockIdx.x * 1024 + t;
    sm[t] = (i < n) ? g_cnt[i] : 0;
    __syncthreads();
    for (int s = 512; s > 0; s >>= 1) {
        if (t < s) sm[t] += sm[t + s];
        __syncthreads();
    }
    if (t == 0) g_bsum[blockIdx.x] = sm[0];
}

__global__ void k_scan_b(int nb) {
    __shared__ int sm[128];
    int t = threadIdx.x;
    if (t < nb) sm[t] = g_bsum[t];
    __syncthreads();
    if (t == 0) {
        int run = 0;
        for (int i = 0; i < nb; i++) { int v = sm[i]; sm[i] = run; run += v; }
    }
    __syncthreads();
    if (t < nb) g_bsum[t] = sm[t];
}

__global__ void k_scan_c(int n, int e) {
    __shared__ int tmp[1024];
    int t = threadIdx.x;
    int i = blockIdx.x * 1024 + t;
    int v = (i < n) ? g_cnt[i] : 0;
    tmp[t] = v;
    __syncthreads();
    // inclusive Hillis-Steele
    for (int d = 1; d < 1024; d <<= 1) {
        int add = (t >= d) ? tmp[t - d] : 0;
        __syncthreads();
        tmp[t] += add;
        __syncthreads();
    }
    if (i < n) {
        int off = g_bsum[blockIdx.x] + tmp[t] - v;   // exclusive
        g_off[i] = off;
        g_cur[i] = off;
        g_dinv[i] = rsqrtf((float)(v + 1));          // +1 self loop
    }
    if (i == 0) g_off[n] = e;
}

__global__ void k_fill(const void* __restrict__ ei, int e, int n) {
    int i = blockIdx.x * blockDim.x + threadIdx.x;
    if (i < e) {
        int r = edge_at(ei, i);                      // row[i]
        int c = edge_at(ei, e + i);                  // col[i]
        if ((unsigned)c < (unsigned)n && (unsigned)r < (unsigned)n) {
            int p = atomicAdd(&g_cur[c], 1);
            if (p < e) g_rows[p] = r;
        }
    }
}

// h1s[n][f] = (x[n] . W1[:,f]) * dinv[n]    (16 nodes / block, 16 threads / node)
__global__ void k_gemm1(const float* __restrict__ x,
                        const float* __restrict__ W1, int n) {
    __shared__ float Ws[INF_ * HID_];        // 8 KB
    __shared__ float Xs[16 * 132];           // padded stride to kill bank conflicts
    int tid = threadIdx.x;
    for (int i = tid; i < INF_ * HID_; i += 256) Ws[i] = W1[i];
    int base = blockIdx.x * 16 * INF_;
    for (int i = tid; i < 16 * INF_; i += 256) {
        int ln = i >> 7, kk = i & 127;
        int gi = base + i;
        Xs[ln * 132 + kk] = (gi < n * INF_) ? x[gi] : 0.f;
    }
    __syncthreads();
    int ln = tid >> 4, f = tid & 15;
    int node = blockIdx.x * 16 + ln;
    if (node < n) {
        float acc = 0.f;
        const float* xr = &Xs[ln * 132];
#pragma unroll 16
        for (int k = 0; k < INF_; k++) acc = fmaf(xr[k], Ws[k * HID_ + f], acc);
        g_h1s[node * HID_ + f] = acc * g_dinv[node];
    }
}

// o1[n][f] = relu(dinv[n]*(h1s[n][f] + sum_{r->n} h1s[r][f]) + b1[f])
__global__ void k_agg1(const float* __restrict__ b1, int n) {
    int tid = threadIdx.x;
    int g = tid >> 4, f = tid & 15;
    int node = blockIdx.x * 16 + g;
    if (node >= n) return;
    int o0 = g_off[node], o1e = g_off[node + 1];
    float s = g_h1s[node * HID_ + f];
    for (int e2 = o0; e2 < o1e; ++e2) {
        int r = __ldg(&g_rows[e2]);
        s += __ldg(&g_h1s[r * HID_ + f]);
    }
    float v = fmaf(s, g_dinv[node], b1[f]);
    g_o1[node * HID_ + f] = fmaxf(v, 0.f);
}

// h2s[n][k] = (o1[n] . W2[:,k]) * dinv[n]   (4 nodes / block, 64 threads / node)
__global__ void k_gemm2(const float* __restrict__ W2, int n) {
    __shared__ float Ws[HID_ * NC_];         // 4 KB
    __shared__ float Os[4 * HID_];
    int tid = threadIdx.x;
    for (int i = tid; i < HID_ * NC_; i += 256) Ws[i] = W2[i];
    int nodeBase = blockIdx.x * 4;
    if (tid < 4 * HID_) {
        int ln = tid >> 4, j = tid & 15;
        int node = nodeBase + ln;
        Os[tid] = (node < n) ? g_o1[node * HID_ + j] : 0.f;
    }
    __syncthreads();
    int ln = tid >> 6, k = tid & 63;
    int node = nodeBase + ln;
    if (node < n) {
        float acc = 0.f;
#pragma unroll
        for (int j = 0; j < HID_; j++) acc = fmaf(Os[ln * HID_ + j], Ws[j * NC_ + k], acc);
        g_h2s[node * NC_ + k] = acc * g_dinv[node];
    }
}

// layer-2 aggregate + bias + relu, fused with global-add-pool (colsum)
__global__ void k_agg2(const float* __restrict__ b2, int n) {
    int tid = threadIdx.x;
    int g = tid >> 6, k = tid & 63;
    float bk = b2[k];
    float accT = 0.f;
    for (int node = blockIdx.x * 4 + g; node < n; node += gridDim.x * 4) {
        int o0 = g_off[node], o1e = g_off[node + 1];
        float s = g_h2s[node * NC_ + k];
        for (int e2 = o0; e2 < o1e; ++e2) {
            int r = __ldg(&g_rows[e2]);
            s += __ldg(&g_h2s[r * NC_ + k]);
        }
        float v = fmaf(s, g_dinv[node], bk);
        accT += fmaxf(v, 0.f);
    }
    __shared__ float red[256];
    red[tid] = accT;
    __syncthreads();
    if (tid < 64) {
        float tot = red[tid] + red[tid + 64] + red[tid + 128] + red[tid + 192];
        atomicAdd(&g_Sacc[tid * 64], tot);   // 256B stride -> spread across L2 slices
    }
}

__global__ void k_final(const float* __restrict__ fcW,
                        const float* __restrict__ fcb,
                        float* __restrict__ out, int n) {
    __shared__ float Ss[NC_];
    int t = threadIdx.x;
    if (t < NC_) Ss[t] = g_Sacc[t * 64];
    __syncthreads();
    if (t == 0) {
        float nf = (float)n;
        float p0 = nf * fcb[0], p1 = nf * fcb[1];
        for (int k = 0; k < NC_; k++) {
            p0 = fmaf(Ss[k], fcW[k * 2 + 0], p0);
            p1 = fmaf(Ss[k], fcW[k * 2 + 1], p1);
        }
        float m = fmaxf(p0, p1);
        float l = m + logf(expf(p0 - m) + expf(p1 - m));
        out[0] = p0 - l;
        out[1] = p1 - l;
    }
}

// ---------------- launcher ----------------
extern "C" void kernel_launch(void* const* d_in, const int* in_sizes, int n_in,
                              void* d_out, int out_size) {
    const float* x   = (const float*)d_in[0];
    const void*  ei  = (const void*)d_in[1];
    const float* W1  = (const float*)d_in[2];
    const float* b1  = (const float*)d_in[3];
    const float* W2  = (const float*)d_in[4];
    const float* b2  = (const float*)d_in[5];
    const float* fcW = (const float*)d_in[6];
    const float* fcb = (const float*)d_in[7];
    float* out = (float*)d_out;

    int n = in_sizes[0] / INF_;   // 100000
    int e = in_sizes[1] / 2;      // 3200000
    if (n > NN) n = NN;
    if (e > EE) e = EE;

    int nbScan = (n + 1023) / 1024;

    k_detect<<<1, 32>>>((const unsigned int*)ei);
    k_init  <<<(n + 255) / 256, 256>>>(n);
    k_count <<<(e + 255) / 256, 256>>>(ei, e, n);
    k_scan_a<<<nbScan, 1024>>>(n);
    k_scan_b<<<1, 128>>>(nbScan);
    k_scan_c<<<nbScan, 1024>>>(n, e);
    k_fill  <<<(e + 255) / 256, 256>>>(ei, e, n);
    k_gemm1 <<<(n + 15) / 16, 256>>>(x, W1, n);
    k_agg1  <<<(n + 15) / 16, 256>>>(b1, n);
    k_gemm2 <<<(n + 3) / 4, 256>>>(W2, n);
    k_agg2  <<<1776, 256>>>(b2, n);
    k_final <<<1, 64>>>(fcW, fcb, out, n);
}

// round 7
// speedup vs baseline: 1.2726x; 1.2726x over previous
#include <cuda_runtime.h>

// Problem constants (fixed by the dataset)
#define NN   100000
#define EE   3200000
#define INF_ 128
#define HID_ 16
#define NC_  64

// ---------------- scratch (static device allocations only) ----------------
__device__ int   g_is64;
__device__ int   g_cnt[NN];
__device__ int   g_off[NN + 1];
__device__ int   g_cur[NN];
__device__ float g_dinv[NN];
__device__ int   g_rows[EE];            // CSR-by-destination source list
__device__ float g_h1s[NN * HID_];      // (x@W1) * dinv
__device__ float g_h2s[NN * NC_];       // (o1@W2) * dinv
__device__ float g_Sacc[NC_ * 64];      // pooled colsum, 256B stride to spread L2 atomics
__device__ int   g_bsum[128];

// ---------------- kernels ----------------

// init counters/pool accumulators + dtype detection (block 0, thread 0).
// int64 data (values < 2^31) has every odd int32 word == 0.
__global__ void k_init(const unsigned int* __restrict__ ei, int n) {
    int i = blockIdx.x * blockDim.x + threadIdx.x;
    if (i < n) g_cnt[i] = 0;
    if (i < NC_ * 64) g_Sacc[i] = 0.f;
    if (blockIdx.x == 0 && threadIdx.x == 0) {
        int all0 = 1;
        for (int j = 0; j < 64; j++)
            if (ei[2 * j + 1] != 0u) { all0 = 0; break; }
        g_is64 = all0;
    }
}

__global__ void k_count(const void* __restrict__ ei, int e, int n) {
    int i = (blockIdx.x * blockDim.x + threadIdx.x) * 4;
    if (i >= e) return;
    if (g_is64) {
        const long long* col = (const long long*)ei + e;
#pragma unroll
        for (int j = 0; j < 4; j++)
            if (i + j < e) {
                int c = (int)col[i + j];
                if ((unsigned)c < (unsigned)n) atomicAdd(&g_cnt[c], 1);
            }
    } else {
        const int* col = (const int*)ei + e;
        if (i + 3 < e) {
            int4 c4 = *(const int4*)(col + i);
            if ((unsigned)c4.x < (unsigned)n) atomicAdd(&g_cnt[c4.x], 1);
            if ((unsigned)c4.y < (unsigned)n) atomicAdd(&g_cnt[c4.y], 1);
            if ((unsigned)c4.z < (unsigned)n) atomicAdd(&g_cnt[c4.z], 1);
            if ((unsigned)c4.w < (unsigned)n) atomicAdd(&g_cnt[c4.w], 1);
        } else {
            for (int j = 0; j < 4 && i + j < e; j++) {
                int c = col[i + j];
                if ((unsigned)c < (unsigned)n) atomicAdd(&g_cnt[c], 1);
            }
        }
    }
}

__global__ void k_scan_a(int n) {
    __shared__ int wsum[32];
    int t = threadIdx.x;
    int i = blockIdx.x * 1024 + t;
    int v = (i < n) ? g_cnt[i] : 0;
#pragma unroll
    for (int s = 16; s > 0; s >>= 1) v += __shfl_down_sync(0xffffffffu, v, s);
    if ((t & 31) == 0) wsum[t >> 5] = v;
    __syncthreads();
    if (t < 32) {
        int x = wsum[t];
#pragma unroll
        for (int s = 16; s > 0; s >>= 1) x += __shfl_down_sync(0xffffffffu, x, s);
        if (t == 0) g_bsum[blockIdx.x] = x;
    }
}

__global__ void k_scan_b(int nb) {
    __shared__ int sm[128];
    int t = threadIdx.x;
    if (t < nb) sm[t] = g_bsum[t];
    __syncthreads();
    if (t == 0) {
        int run = 0;
        for (int i = 0; i < nb; i++) { int v = sm[i]; sm[i] = run; run += v; }
    }
    __syncthreads();
    if (t < nb) g_bsum[t] = sm[t];
}

__global__ void k_scan_c(int n, int e) {
    __shared__ int wsum[32];
    __shared__ int wpre[32];
    int t = threadIdx.x, lane = t & 31, wid = t >> 5;
    int i = blockIdx.x * 1024 + t;
    int v = (i < n) ? g_cnt[i] : 0;
    int incl = v;
#pragma unroll
    for (int d = 1; d < 32; d <<= 1) {
        int u = __shfl_up_sync(0xffffffffu, incl, d);
        if (lane >= d) incl += u;
    }
    if (lane == 31) wsum[wid] = incl;
    __syncthreads();
    if (t < 32) {
        int x = wsum[t];
        int xi = x;
#pragma unroll
        for (int d = 1; d < 32; d <<= 1) {
            int u = __shfl_up_sync(0xffffffffu, xi, d);
            if (t >= d) xi += u;
        }
        wpre[t] = xi - x;   // exclusive prefix of warp sums
    }
    __syncthreads();
    if (i < n) {
        int off = g_bsum[blockIdx.x] + wpre[wid] + incl - v;  // exclusive
        g_off[i] = off;
        g_cur[i] = off;
        g_dinv[i] = rsqrtf((float)(v + 1));                   // +1 self loop
    }
    if (i == 0) g_off[n] = e;
}

__global__ void k_fill(const void* __restrict__ ei, int e, int n) {
    int i = (blockIdx.x * blockDim.x + threadIdx.x) * 4;
    if (i >= e) return;
    int r[4], c[4], m = (e - i < 4) ? (e - i) : 4;
    if (g_is64) {
        const long long* row = (const long long*)ei;
        const long long* col = row + e;
        for (int j = 0; j < m; j++) { r[j] = (int)row[i + j]; c[j] = (int)col[i + j]; }
    } else {
        const int* row = (const int*)ei;
        const int* col = row + e;
        if (m == 4) {
            int4 r4 = *(const int4*)(row + i);
            int4 c4 = *(const int4*)(col + i);
            r[0] = r4.x; r[1] = r4.y; r[2] = r4.z; r[3] = r4.w;
            c[0] = c4.x; c[1] = c4.y; c[2] = c4.z; c[3] = c4.w;
        } else {
            for (int j = 0; j < m; j++) { r[j] = row[i + j]; c[j] = col[i + j]; }
        }
    }
    for (int j = 0; j < m; j++) {
        if ((unsigned)c[j] < (unsigned)n && (unsigned)r[j] < (unsigned)n) {
            int p = atomicAdd(&g_cur[c[j]], 1);
            if (p < e) g_rows[p] = r[j];
        }
    }
}

// h1s[n][f] = (x[n] . W1[:,f]) * dinv[n]
// Block: 256 threads = 4 f-groups x 64 q; each thread owns 2 nodes (q, q+64)
// and 4 consecutive f-columns -> W1 read once per k as a broadcast float4.
__global__ void k_gemm1(const float* __restrict__ x,
                        const float* __restrict__ W1, int n) {
    __shared__ __align__(16) float Ws[INF_ * HID_];   // 8 KB, [k][f]
    __shared__ float Xs[128 * 65];                     // 33.3 KB, stride 65 (odd)
    int tid = threadIdx.x;
    int fg = tid >> 6;          // 0..3
    int q  = tid & 63;          // 0..63
    int base = blockIdx.x * 128;

    for (int i = tid; i < INF_ * HID_; i += 256) Ws[i] = W1[i];

    float4 a0 = {0.f, 0.f, 0.f, 0.f};
    float4 a1 = {0.f, 0.f, 0.f, 0.f};

    for (int kc = 0; kc < 2; kc++) {
        __syncthreads();
        // stage 128 nodes x 64 k-values
        for (int idx = tid; idx < 128 * 16; idx += 256) {
            int row = idx >> 4, c4 = idx & 15;
            int node = base + row;
            float4 v = {0.f, 0.f, 0.f, 0.f};
            if (node < n) v = *(const float4*)&x[node * INF_ + kc * 64 + c4 * 4];
            float* dst = &Xs[row * 65 + c4 * 4];
            dst[0] = v.x; dst[1] = v.y; dst[2] = v.z; dst[3] = v.w;
        }
        __syncthreads();
#pragma unroll 8
        for (int k = 0; k < 64; k++) {
            float xv0 = Xs[q * 65 + k];
            float xv1 = Xs[(q + 64) * 65 + k];
            float4 w4 = *(const float4*)&Ws[(kc * 64 + k) * HID_ + fg * 4];
            a0.x = fmaf(xv0, w4.x, a0.x); a0.y = fmaf(xv0, w4.y, a0.y);
            a0.z = fmaf(xv0, w4.z, a0.z); a0.w = fmaf(xv0, w4.w, a0.w);
            a1.x = fmaf(xv1, w4.x, a1.x); a1.y = fmaf(xv1, w4.y, a1.y);
            a1.z = fmaf(xv1, w4.z, a1.z); a1.w = fmaf(xv1, w4.w, a1.w);
        }
    }
    int n0 = base + q, n1 = base + q + 64;
    if (n0 < n) {
        float d = g_dinv[n0];
        a0.x *= d; a0.y *= d; a0.z *= d; a0.w *= d;
        *(float4*)&g_h1s[n0 * HID_ + fg * 4] = a0;
    }
    if (n1 < n) {
        float d = g_dinv[n1];
        a1.x *= d; a1.y *= d; a1.z *= d; a1.w *= d;
        *(float4*)&g_h1s[n1 * HID_ + fg * 4] = a1;
    }
}

// Fused: layer-1 aggregate+relu (o1 kept in smem) then gemm2 -> h2s.
// 256 threads, 32 nodes/block. Phase A: 8 lanes x float2 per node.
// Phase B: 8 threads/node, each computes 8 of the 64 outputs via float4 W2.
__global__ void k_fused(const float* __restrict__ b1,
                        const float* __restrict__ W2, int n) {
    __shared__ __align__(16) float Ws[HID_ * NC_];   // 4 KB, [j][k]
    __shared__ float O1[32 * 17];
    int tid = threadIdx.x, lane = tid & 31, w = tid >> 5;
    for (int i = tid; i < HID_ * NC_; i += 256) Ws[i] = W2[i];

    int g = lane >> 3, t = lane & 7;
    int nl = w * 4 + g;
    int node = blockIdx.x * 32 + nl;
    if (node < n) {
        const float2* h1 = (const float2*)g_h1s;
        float2 s = h1[node * 8 + t];
        int e0 = g_off[node], e1 = g_off[node + 1];
        int e = e0;
        for (; e + 1 < e1; e += 2) {
            int r0 = __ldg(&g_rows[e]), r1 = __ldg(&g_rows[e + 1]);
            float2 a = h1[r0 * 8 + t], b = h1[r1 * 8 + t];
            s.x += a.x + b.x; s.y += a.y + b.y;
        }
        if (e < e1) {
            int r0 = __ldg(&g_rows[e]);
            float2 a = h1[r0 * 8 + t];
            s.x += a.x; s.y += a.y;
        }
        float d = g_dinv[node];
        float2 bb = ((const float2*)b1)[t];
        O1[nl * 17 + 2 * t]     = fmaxf(fmaf(s.x, d, bb.x), 0.f);
        O1[nl * 17 + 2 * t + 1] = fmaxf(fmaf(s.y, d, bb.y), 0.f);
    }
    __syncthreads();

    int nl2 = tid >> 3, t2 = tid & 7;
    int node2 = blockIdx.x * 32 + nl2;
    if (node2 < n) {
        float4 a0 = {0.f,0.f,0.f,0.f}, a1 = {0.f,0.f,0.f,0.f};
#pragma unroll
        for (int j = 0; j < HID_; j++) {
            float o = O1[nl2 * 17 + j];
            const float4* wr = (const float4*)&Ws[j * NC_ + t2 * 8];
            float4 w0 = wr[0], w1 = wr[1];
            a0.x = fmaf(o, w0.x, a0.x); a0.y = fmaf(o, w0.y, a0.y);
            a0.z = fmaf(o, w0.z, a0.z); a0.w = fmaf(o, w0.w, a0.w);
            a1.x = fmaf(o, w1.x, a1.x); a1.y = fmaf(o, w1.y, a1.y);
            a1.z = fmaf(o, w1.z, a1.z); a1.w = fmaf(o, w1.w, a1.w);
        }
        float d2 = g_dinv[node2];
        a0.x *= d2; a0.y *= d2; a0.z *= d2; a0.w *= d2;
        a1.x *= d2; a1.y *= d2; a1.z *= d2; a1.w *= d2;
        float4* out = (float4*)&g_h2s[node2 * NC_ + t2 * 8];
        out[0] = a0; out[1] = a1;
    }
}

// Layer-2 aggregate + bias + relu, fused with global-add-pool.
// One warp per node, lane holds features (2t, 2t+1) via float2, edge loop
// unrolled x4 with index prefetch for MLP.
__global__ void k_agg2(const float* __restrict__ b2, int n) {
    int tid = threadIdx.x, lane = tid & 31, w = tid >> 5;
    const float2* h2 = (const float2*)g_h2s;
    float2 bb = ((const float2*)b2)[lane];
    float2 acc = {0.f, 0.f};
    for (int node = blockIdx.x * 8 + w; node < n; node += gridDim.x * 8) {
        int e0 = g_off[node], e1 = g_off[node + 1];
        float2 s = h2[node * 32 + lane];
        int e = e0;
        for (; e + 3 < e1; e += 4) {
            int r0 = __ldg(&g_rows[e]),     r1 = __ldg(&g_rows[e + 1]);
            int r2 = __ldg(&g_rows[e + 2]), r3 = __ldg(&g_rows[e + 3]);
            float2 a = h2[r0 * 32 + lane], b = h2[r1 * 32 + lane];
            float2 c = h2[r2 * 32 + lane], d = h2[r3 * 32 + lane];
            s.x += (a.x + b.x) + (c.x + d.x);
            s.y += (a.y + b.y) + (c.y + d.y);
        }
        for (; e < e1; e++) {
            int r0 = __ldg(&g_rows[e]);
            float2 a = h2[r0 * 32 + lane];
            s.x += a.x; s.y += a.y;
        }
        float dv = g_dinv[node];
        acc.x += fmaxf(fmaf(s.x, dv, bb.x), 0.f);
        acc.y += fmaxf(fmaf(s.y, dv, bb.y), 0.f);
    }
    __shared__ float red[8][64];
    red[w][2 * lane]     = acc.x;
    red[w][2 * lane + 1] = acc.y;
    __syncthreads();
    if (tid < 64) {
        float tot = 0.f;
#pragma unroll
        for (int i = 0; i < 8; i++) tot += red[i][tid];
        atomicAdd(&g_Sacc[tid * 64], tot);   // 256B stride spreads L2 slices
    }
}

__global__ void k_final(const float* __restrict__ fcW,
                        const float* __restrict__ fcb,
                        float* __restrict__ out, int n) {
    __shared__ float Ss[NC_];
    int t = threadIdx.x;
    if (t < NC_) Ss[t] = g_Sacc[t * 64];
    __syncthreads();
    if (t == 0) {
        float nf = (float)n;
        float p0 = nf * fcb[0], p1 = nf * fcb[1];
        for (int k = 0; k < NC_; k++) {
            p0 = fmaf(Ss[k], fcW[k * 2 + 0], p0);
            p1 = fmaf(Ss[k], fcW[k * 2 + 1], p1);
        }
        float m = fmaxf(p0, p1);
        float l = m + logf(expf(p0 - m) + expf(p1 - m));
        out[0] = p0 - l;
        out[1] = p1 - l;
    }
}

// ---------------- launcher ----------------
extern "C" void kernel_launch(void* const* d_in, const int* in_sizes, int n_in,
                              void* d_out, int out_size) {
    const float* x   = (const float*)d_in[0];
    const void*  ei  = (const void*)d_in[1];
    const float* W1  = (const float*)d_in[2];
    const float* b1  = (const float*)d_in[3];
    const float* W2  = (const float*)d_in[4];
    const float* b2  = (const float*)d_in[5];
    const float* fcW = (const float*)d_in[6];
    const float* fcb = (const float*)d_in[7];
    float* out = (float*)d_out;

    int n = in_sizes[0] / INF_;   // 100000
    int e = in_sizes[1] / 2;      // 3200000
    if (n > NN) n = NN;
    if (e > EE) e = EE;

    int nbScan  = (n + 1023) / 1024;
    int nbEdge4 = (e + 1023) / 1024;   // 4 edges/thread, 256 threads

    k_init  <<<(n + 255) / 256, 256>>>((const unsigned int*)ei, n);
    k_count <<<nbEdge4, 256>>>(ei, e, n);
    k_scan_a<<<nbScan, 1024>>>(n);
    k_scan_b<<<1, 128>>>(nbScan);
    k_scan_c<<<nbScan, 1024>>>(n, e);
    k_fill  <<<nbEdge4, 256>>>(ei, e, n);
    k_gemm1 <<<(n + 127) / 128, 256>>>(x, W1, n);
    k_fused <<<(n + 31) / 32, 256>>>(b1, W2, n);
    k_agg2  <<<1184, 256>>>(b2, n);
    k_final <<<1, 64>>>(fcW, fcb, out, n);
}

// round 8
// speedup vs baseline: 1.5549x; 1.2218x over previous
#include <cuda_runtime.h>

// Problem constants (fixed by the dataset)
#define NN   100000
#define EE   3200000
#define INF_ 128
#define HID_ 16
#define NC_  64

// ---------------- scratch (static device allocations only) ----------------
__device__ int   g_is64;
__device__ int   g_done;
__device__ int   g_cnt[NN];
__device__ int   g_off[NN + 1];
__device__ int   g_cur[NN];
__device__ float g_dinv[NN];
__device__ int   g_rows[EE];            // CSR-by-destination source list
__device__ float g_h1s[NN * HID_];      // (x@W1) * dinv
__device__ float g_o1s[NN * HID_];      // relu(layer1) * dinv (pre-scaled source)
__device__ float g_Sacc[NC_ * 64];      // pooled colsum, 256B stride to spread L2 atomics
__device__ int   g_bsum[128];

// ---------------- kernels ----------------

// init counters/pool accumulators + dtype detection.
// int64 data (values < 2^31) has every odd int32 word == 0.
__global__ void k_init(const unsigned int* __restrict__ ei, int n) {
    int i = blockIdx.x * blockDim.x + threadIdx.x;
    if (i < n) g_cnt[i] = 0;
    if (i < NC_ * 64) g_Sacc[i] = 0.f;
    if (blockIdx.x == 0 && threadIdx.x == 0) {
        int all0 = 1;
        for (int j = 0; j < 64; j++)
            if (ei[2 * j + 1] != 0u) { all0 = 0; break; }
        g_is64 = all0;
        g_done = 0;
    }
}

__global__ void k_count(const void* __restrict__ ei, int e, int n) {
    int i = (blockIdx.x * blockDim.x + threadIdx.x) * 4;
    if (i >= e) return;
    if (g_is64) {
        const long long* col = (const long long*)ei + e;
#pragma unroll
        for (int j = 0; j < 4; j++)
            if (i + j < e) {
                int c = (int)col[i + j];
                if ((unsigned)c < (unsigned)n) atomicAdd(&g_cnt[c], 1);
            }
    } else {
        const int* col = (const int*)ei + e;
        if (i + 3 < e) {
            int4 c4 = *(const int4*)(col + i);
            if ((unsigned)c4.x < (unsigned)n) atomicAdd(&g_cnt[c4.x], 1);
            if ((unsigned)c4.y < (unsigned)n) atomicAdd(&g_cnt[c4.y], 1);
            if ((unsigned)c4.z < (unsigned)n) atomicAdd(&g_cnt[c4.z], 1);
            if ((unsigned)c4.w < (unsigned)n) atomicAdd(&g_cnt[c4.w], 1);
        } else {
            for (int j = 0; j < 4 && i + j < e; j++) {
                int c = col[i + j];
                if ((unsigned)c < (unsigned)n) atomicAdd(&g_cnt[c], 1);
            }
        }
    }
}

__global__ void k_scan_a(int n) {
    __shared__ int wsum[32];
    int t = threadIdx.x;
    int i = blockIdx.x * 1024 + t;
    int v = (i < n) ? g_cnt[i] : 0;
#pragma unroll
    for (int s = 16; s > 0; s >>= 1) v += __shfl_down_sync(0xffffffffu, v, s);
    if ((t & 31) == 0) wsum[t >> 5] = v;
    __syncthreads();
    if (t < 32) {
        int x = wsum[t];
#pragma unroll
        for (int s = 16; s > 0; s >>= 1) x += __shfl_down_sync(0xffffffffu, x, s);
        if (t == 0) g_bsum[blockIdx.x] = x;
    }
}

// Per-block scan; block offset computed in-kernel from g_bsum (no k_scan_b launch).
__global__ void k_scan_c(int n, int e) {
    __shared__ int wsum[32];
    __shared__ int wpre[32];
    __shared__ int blockOff;
    int t = threadIdx.x, lane = t & 31, wid = t >> 5;
    int i = blockIdx.x * 1024 + t;
    if (t < 32) {
        int s = 0;
        for (int j = t; j < blockIdx.x; j += 32) s += g_bsum[j];
#pragma unroll
        for (int d = 16; d > 0; d >>= 1) s += __shfl_down_sync(0xffffffffu, s, d);
        if (t == 0) blockOff = s;
    }
    int v = (i < n) ? g_cnt[i] : 0;
    int incl = v;
#pragma unroll
    for (int d = 1; d < 32; d <<= 1) {
        int u = __shfl_up_sync(0xffffffffu, incl, d);
        if (lane >= d) incl += u;
    }
    if (lane == 31) wsum[wid] = incl;
    __syncthreads();
    if (t < 32) {
        int x = wsum[t];
        int xi = x;
#pragma unroll
        for (int d = 1; d < 32; d <<= 1) {
            int u = __shfl_up_sync(0xffffffffu, xi, d);
            if (t >= d) xi += u;
        }
        wpre[t] = xi - x;   // exclusive prefix of warp sums
    }
    __syncthreads();
    if (i < n) {
        int off = blockOff + wpre[wid] + incl - v;  // exclusive
        g_off[i] = off;
        g_cur[i] = off;
        g_dinv[i] = rsqrtf((float)(v + 1));         // +1 self loop
    }
    if (i == 0) g_off[n] = e;
}

__global__ void k_fill(const void* __restrict__ ei, int e, int n) {
    int i = (blockIdx.x * blockDim.x + threadIdx.x) * 4;
    if (i >= e) return;
    int r[4], c[4], m = (e - i < 4) ? (e - i) : 4;
    if (g_is64) {
        const long long* row = (const long long*)ei;
        const long long* col = row + e;
        for (int j = 0; j < m; j++) { r[j] = (int)row[i + j]; c[j] = (int)col[i + j]; }
    } else {
        const int* row = (const int*)ei;
        const int* col = row + e;
        if (m == 4) {
            int4 r4 = *(const int4*)(row + i);
            int4 c4 = *(const int4*)(col + i);
            r[0] = r4.x; r[1] = r4.y; r[2] = r4.z; r[3] = r4.w;
            c[0] = c4.x; c[1] = c4.y; c[2] = c4.z; c[3] = c4.w;
        } else {
            for (int j = 0; j < m; j++) { r[j] = row[i + j]; c[j] = col[i + j]; }
        }
    }
    for (int j = 0; j < m; j++) {
        if ((unsigned)c[j] < (unsigned)n && (unsigned)r[j] < (unsigned)n) {
            int p = atomicAdd(&g_cur[c[j]], 1);
            if (p < e) g_rows[p] = r[j];
        }
    }
}

// h1s[n][f] = (x[n] . W1[:,f]) * dinv[n]
// 256 threads = 4 f-groups x 64 q; each thread owns 2 nodes (q, q+64),
// 4 consecutive f-columns; W1 broadcast as float4.
__global__ void k_gemm1(const float* __restrict__ x,
                        const float* __restrict__ W1, int n) {
    __shared__ __align__(16) float Ws[INF_ * HID_];   // 8 KB, [k][f]
    __shared__ float Xs[128 * 65];                    // stride 65
    int tid = threadIdx.x;
    int fg = tid >> 6;          // 0..3
    int q  = tid & 63;          // 0..63
    int base = blockIdx.x * 128;

    for (int i = tid; i < INF_ * HID_; i += 256) Ws[i] = W1[i];

    float4 a0 = {0.f, 0.f, 0.f, 0.f};
    float4 a1 = {0.f, 0.f, 0.f, 0.f};

    for (int kc = 0; kc < 2; kc++) {
        __syncthreads();
        for (int idx = tid; idx < 128 * 16; idx += 256) {
            int row = idx >> 4, c4 = idx & 15;
            int node = base + row;
            float4 v = {0.f, 0.f, 0.f, 0.f};
            if (node < n) v = *(const float4*)&x[node * INF_ + kc * 64 + c4 * 4];
            float* dst = &Xs[row * 65 + c4 * 4];
            dst[0] = v.x; dst[1] = v.y; dst[2] = v.z; dst[3] = v.w;
        }
        __syncthreads();
#pragma unroll 8
        for (int k = 0; k < 64; k++) {
            float xv0 = Xs[q * 65 + k];
            float xv1 = Xs[(q + 64) * 65 + k];
            float4 w4 = *(const float4*)&Ws[(kc * 64 + k) * HID_ + fg * 4];
            a0.x = fmaf(xv0, w4.x, a0.x); a0.y = fmaf(xv0, w4.y, a0.y);
            a0.z = fmaf(xv0, w4.z, a0.z); a0.w = fmaf(xv0, w4.w, a0.w);
            a1.x = fmaf(xv1, w4.x, a1.x); a1.y = fmaf(xv1, w4.y, a1.y);
            a1.z = fmaf(xv1, w4.z, a1.z); a1.w = fmaf(xv1, w4.w, a1.w);
        }
    }
    int n0 = base + q, n1 = base + q + 64;
    if (n0 < n) {
        float d = g_dinv[n0];
        a0.x *= d; a0.y *= d; a0.z *= d; a0.w *= d;
        *(float4*)&g_h1s[n0 * HID_ + fg * 4] = a0;
    }
    if (n1 < n) {
        float d = g_dinv[n1];
        a1.x *= d; a1.y *= d; a1.z *= d; a1.w *= d;
        *(float4*)&g_h1s[n1 * HID_ + fg * 4] = a1;
    }
}

// Layer-1 aggregate + relu, pre-scaled for next layer:
// o1s[n][f] = relu(dinv[n]*(h1s[n][f] + sum_r h1s[r][f]) + b1[f]) * dinv[n]
// 256 threads, 32 nodes/block, 8 lanes x float2 per node, x4 unroll.
__global__ void k_agg1f(const float* __restrict__ b1, int n) {
    int tid = threadIdx.x, lane = tid & 31, w = tid >> 5;
    int g = lane >> 3, t = lane & 7;
    int node = blockIdx.x * 32 + w * 4 + g;
    if (node >= n) return;
    const float2* h1 = (const float2*)g_h1s;
    float2 s = h1[node * 8 + t];
    int e0 = g_off[node], e1 = g_off[node + 1];
    int e = e0;
    for (; e + 3 < e1; e += 4) {
        int r0 = __ldg(&g_rows[e]),     r1 = __ldg(&g_rows[e + 1]);
        int r2 = __ldg(&g_rows[e + 2]), r3 = __ldg(&g_rows[e + 3]);
        float2 a = h1[r0 * 8 + t], b = h1[r1 * 8 + t];
        float2 c = h1[r2 * 8 + t], d = h1[r3 * 8 + t];
        s.x += (a.x + b.x) + (c.x + d.x);
        s.y += (a.y + b.y) + (c.y + d.y);
    }
    for (; e < e1; e++) {
        int r0 = __ldg(&g_rows[e]);
        float2 a = h1[r0 * 8 + t];
        s.x += a.x; s.y += a.y;
    }
    float d = g_dinv[node];
    float2 bb = ((const float2*)b1)[t];
    float2 o;
    o.x = fmaxf(fmaf(s.x, d, bb.x), 0.f) * d;
    o.y = fmaxf(fmaf(s.y, d, bb.y), 0.f) * d;
    ((float2*)g_o1s)[node * 8 + t] = o;
}

// Layer-2 fully fused: 16-dim aggregate (Â commutes with W2), then per-node
// GEMM 16->64 + bias + relu, accumulated into the global pool. Last block
// performs fc + log_softmax epilogue. Gather = 64B/edge instead of 256B.
__global__ void k_agg2f(const float* __restrict__ b2,
                        const float* __restrict__ W2,
                        const float* __restrict__ fcW,
                        const float* __restrict__ fcb,
                        float* __restrict__ out, int n) {
    __shared__ __align__(16) float Ws[HID_ * NC_];   // 4 KB, [j][k]
    __shared__ float A16[32 * 17];
    __shared__ float red[32 * 65];
    int tid = threadIdx.x, lane = tid & 31, w = tid >> 5;
    for (int i = tid; i < HID_ * NC_; i += 256) Ws[i] = W2[i];

    int gA = lane >> 3, tA = lane & 7;         // phase-A mapping
    int nlA = w * 4 + gA;
    int nlB = tid >> 3, tB = tid & 7;          // phase-B mapping
    float4 bb0 = ((const float4*)b2)[tB * 2];
    float4 bb1 = ((const float4*)b2)[tB * 2 + 1];
    float4 acc0 = {0.f, 0.f, 0.f, 0.f};
    float4 acc1 = {0.f, 0.f, 0.f, 0.f};

    int ntiles = (n + 31) / 32;
    const float2* o1 = (const float2*)g_o1s;

    for (int tile = blockIdx.x; tile < ntiles; tile += gridDim.x) {
        __syncthreads();                        // protect A16 reuse
        int node = tile * 32 + nlA;
        if (node < n) {
            float2 s = o1[node * 8 + tA];
            int e0 = g_off[node], e1 = g_off[node + 1];
            int e = e0;
            for (; e + 3 < e1; e += 4) {
                int r0 = __ldg(&g_rows[e]),     r1 = __ldg(&g_rows[e + 1]);
                int r2 = __ldg(&g_rows[e + 2]), r3 = __ldg(&g_rows[e + 3]);
                float2 a = o1[r0 * 8 + tA], b = o1[r1 * 8 + tA];
                float2 c = o1[r2 * 8 + tA], d = o1[r3 * 8 + tA];
                s.x += (a.x + b.x) + (c.x + d.x);
                s.y += (a.y + b.y) + (c.y + d.y);
            }
            for (; e < e1; e++) {
                int r0 = __ldg(&g_rows[e]);
                float2 a = o1[r0 * 8 + tA];
                s.x += a.x; s.y += a.y;
            }
            float d = g_dinv[node];
            A16[nlA * 17 + 2 * tA]     = s.x * d;
            A16[nlA * 17 + 2 * tA + 1] = s.y * d;
        }
        __syncthreads();
        int node2 = tile * 32 + nlB;
        if (node2 < n) {
            float4 p0 = bb0, p1 = bb1;
#pragma unroll
            for (int j = 0; j < HID_; j++) {
                float o = A16[nlB * 17 + j];
                const float4* wr = (const float4*)&Ws[j * NC_ + tB * 8];
                float4 w0 = wr[0], w1 = wr[1];
                p0.x = fmaf(o, w0.x, p0.x); p0.y = fmaf(o, w0.y, p0.y);
                p0.z = fmaf(o, w0.z, p0.z); p0.w = fmaf(o, w0.w, p0.w);
                p1.x = fmaf(o, w1.x, p1.x); p1.y = fmaf(o, w1.y, p1.y);
                p1.z = fmaf(o, w1.z, p1.z); p1.w = fmaf(o, w1.w, p1.w);
            }
            acc0.x += fmaxf(p0.x, 0.f); acc0.y += fmaxf(p0.y, 0.f);
            acc0.z += fmaxf(p0.z, 0.f); acc0.w += fmaxf(p0.w, 0.f);
            acc1.x += fmaxf(p1.x, 0.f); acc1.y += fmaxf(p1.y, 0.f);
            acc1.z += fmaxf(p1.z, 0.f); acc1.w += fmaxf(p1.w, 0.f);
        }
    }

    // block-level pool reduce
    __syncthreads();
    float* rr = &red[nlB * 65 + tB * 8];
    rr[0] = acc0.x; rr[1] = acc0.y; rr[2] = acc0.z; rr[3] = acc0.w;
    rr[4] = acc1.x; rr[5] = acc1.y; rr[6] = acc1.z; rr[7] = acc1.w;
    __syncthreads();
    if (tid < 64) {
        float tot = 0.f;
#pragma unroll
        for (int i = 0; i < 32; i++) tot += red[i * 65 + tid];
        atomicAdd(&g_Sacc[tid * 64], tot);   // 256B stride spreads L2 slices
    }

    // last block computes the epilogue
    __threadfence();
    __shared__ int amLast;
    if (tid == 0) amLast = (atomicAdd(&g_done, 1) == gridDim.x - 1);
    __syncthreads();
    if (amLast && tid == 0) {
        float nf = (float)n;
        float p0 = nf * fcb[0], p1 = nf * fcb[1];
        for (int k = 0; k < NC_; k++) {
            float sv = g_Sacc[k * 64];
            p0 = fmaf(sv, fcW[k * 2 + 0], p0);
            p1 = fmaf(sv, fcW[k * 2 + 1], p1);
        }
        float m = fmaxf(p0, p1);
        float l = m + logf(expf(p0 - m) + expf(p1 - m));
        out[0] = p0 - l;
        out[1] = p1 - l;
    }
}

// ---------------- launcher ----------------
extern "C" void kernel_launch(void* const* d_in, const int* in_sizes, int n_in,
                              void* d_out, int out_size) {
    const float* x   = (const float*)d_in[0];
    const void*  ei  = (const void*)d_in[1];
    const float* W1  = (const float*)d_in[2];
    const float* b1  = (const float*)d_in[3];
    const float* W2  = (const float*)d_in[4];
    const float* b2  = (const float*)d_in[5];
    const float* fcW = (const float*)d_in[6];
    const float* fcb = (const float*)d_in[7];
    float* out = (float*)d_out;

    int n = in_sizes[0] / INF_;   // 100000
    int e = in_sizes[1] / 2;      // 3200000
    if (n > NN) n = NN;
    if (e > EE) e = EE;

    int nbScan  = (n + 1023) / 1024;
    int nbEdge4 = (e + 1023) / 1024;   // 4 edges/thread, 256 threads

    k_init  <<<(n + 255) / 256, 256>>>((const unsigned int*)ei, n);
    k_count <<<nbEdge4, 256>>>(ei, e, n);
    k_scan_a<<<nbScan, 1024>>>(n);
    k_scan_c<<<nbScan, 1024>>>(n, e);
    k_fill  <<<nbEdge4, 256>>>(ei, e, n);
    k_gemm1 <<<(n + 127) / 128, 256>>>(x, W1, n);
    k_agg1f <<<(n + 31) / 32, 256>>>(b1, n);
    k_agg2f <<<1184, 256>>>(b2, W2, fcW, fcb, out, n);
}

// round 13
// speedup vs baseline: 1.5726x; 1.0114x over previous
#include <cuda_runtime.h>
#include <cuda_fp16.h>

// Problem constants (fixed by the dataset)
#define NN   100000
#define EE   3200000
#define INF_ 128
#define HID_ 16
#define NC_  64

// ---------------- scratch (static device allocations only) ----------------
__device__ int     g_is64;
__device__ int     g_done;
__device__ int     g_cnt[NN];
__device__ int     g_off[NN + 1];
__device__ int     g_cur[NN];
__device__ float   g_dinv[NN];
__device__ int     g_rows[EE];          // CSR-by-destination source list
__device__ __half2 g_h1s[NN * 8];       // (x@W1)*dinv, fp16 pairs (32B/node)
__device__ __half2 g_o1s[NN * 8];       // relu(layer1)*dinv, fp16 pairs
__device__ float   g_Sacc[NC_ * 64];    // pooled colsum, 256B stride spreads L2 slices
__device__ int     g_bsum[128];

// ---------------- kernels ----------------

// init counters/pool accumulators + dtype detection.
// int64 data (values < 2^31) has every odd int32 word == 0.
__global__ void k_init(const unsigned int* __restrict__ ei, int n) {
    int i = blockIdx.x * blockDim.x + threadIdx.x;
    if (i < n) g_cnt[i] = 0;
    if (i < NC_ * 64) g_Sacc[i] = 0.f;
    if (blockIdx.x == 0 && threadIdx.x == 0) {
        int all0 = 1;
        for (int j = 0; j < 64; j++)
            if (ei[2 * j + 1] != 0u) { all0 = 0; break; }
        g_is64 = all0;
        g_done = 0;
    }
}

__global__ void k_count(const void* __restrict__ ei, int e, int n) {
    int i = (blockIdx.x * blockDim.x + threadIdx.x) * 4;
    if (i >= e) return;
    if (g_is64) {
        const long long* col = (const long long*)ei + e;
#pragma unroll
        for (int j = 0; j < 4; j++)
            if (i + j < e) {
                int c = (int)col[i + j];
                if ((unsigned)c < (unsigned)n) atomicAdd(&g_cnt[c], 1);
            }
    } else {
        const int* col = (const int*)ei + e;
        if (i + 3 < e) {
            int4 c4 = *(const int4*)(col + i);
            if ((unsigned)c4.x < (unsigned)n) atomicAdd(&g_cnt[c4.x], 1);
            if ((unsigned)c4.y < (unsigned)n) atomicAdd(&g_cnt[c4.y], 1);
            if ((unsigned)c4.z < (unsigned)n) atomicAdd(&g_cnt[c4.z], 1);
            if ((unsigned)c4.w < (unsigned)n) atomicAdd(&g_cnt[c4.w], 1);
        } else {
            for (int j = 0; j < 4 && i + j < e; j++) {
                int c = col[i + j];
                if ((unsigned)c < (unsigned)n) atomicAdd(&g_cnt[c], 1);
            }
        }
    }
}

// per-1024-chunk sums; 256 threads, int4 per thread.
__global__ void k_scan_a(int n) {
    __shared__ int wsum[8];
    int t = threadIdx.x;
    int i = blockIdx.x * 1024 + t * 4;
    int v = 0;
    if (i + 3 < n) {
        int4 c = *(const int4*)&g_cnt[i];
        v = c.x + c.y + c.z + c.w;
    } else {
        for (int j = 0; j < 4 && i + j < n; j++) v += g_cnt[i + j];
    }
#pragma unroll
    for (int s = 16; s > 0; s >>= 1) v += __shfl_down_sync(0xffffffffu, v, s);
    if ((t & 31) == 0) wsum[t >> 5] = v;
    __syncthreads();
    if (t < 32) {
        int x = (t < 8) ? wsum[t] : 0;
#pragma unroll
        for (int s = 4; s > 0; s >>= 1) x += __shfl_down_sync(0xffffffffu, x, s);
        if (t == 0) g_bsum[blockIdx.x] = x;
    }
}

// Per-block scan; block offset computed in-kernel from g_bsum.
__global__ void k_scan_c(int n, int e) {
    __shared__ int wsum[32];
    __shared__ int wpre[32];
    __shared__ int blockOff;
    int t = threadIdx.x, lane = t & 31, wid = t >> 5;
    int i = blockIdx.x * 1024 + t;
    if (t < 32) {
        int s = 0;
        for (int j = t; j < blockIdx.x; j += 32) s += g_bsum[j];
#pragma unroll
        for (int d = 16; d > 0; d >>= 1) s += __shfl_down_sync(0xffffffffu, s, d);
        if (t == 0) blockOff = s;
    }
    int v = (i < n) ? g_cnt[i] : 0;
    int incl = v;
#pragma unroll
    for (int d = 1; d < 32; d <<= 1) {
        int u = __shfl_up_sync(0xffffffffu, incl, d);
        if (lane >= d) incl += u;
    }
    if (lane == 31) wsum[wid] = incl;
    __syncthreads();
    if (t < 32) {
        int x = wsum[t];
        int xi = x;
#pragma unroll
        for (int d = 1; d < 32; d <<= 1) {
            int u = __shfl_up_sync(0xffffffffu, xi, d);
            if (t >= d) xi += u;
        }
        wpre[t] = xi - x;
    }
    __syncthreads();
    if (i < n) {
        int off = blockOff + wpre[wid] + incl - v;  // exclusive
        g_off[i] = off;
        g_cur[i] = off;
        g_dinv[i] = rsqrtf((float)(v + 1));         // +1 self loop
    }
    if (i == 0) g_off[n] = e;
}

__global__ void k_fill(const void* __restrict__ ei, int e, int n) {
    int i = (blockIdx.x * blockDim.x + threadIdx.x) * 4;
    if (i >= e) return;
    int r[4], c[4], m = (e - i < 4) ? (e - i) : 4;
    if (g_is64) {
        const long long* row = (const long long*)ei;
        const long long* col = row + e;
        for (int j = 0; j < m; j++) { r[j] = (int)row[i + j]; c[j] = (int)col[i + j]; }
    } else {
        const int* row = (const int*)ei;
        const int* col = row + e;
        if (m == 4) {
            int4 r4 = *(const int4*)(row + i);
            int4 c4 = *(const int4*)(col + i);
            r[0] = r4.x; r[1] = r4.y; r[2] = r4.z; r[3] = r4.w;
            c[0] = c4.x; c[1] = c4.y; c[2] = c4.z; c[3] = c4.w;
        } else {
            for (int j = 0; j < m; j++) { r[j] = row[i + j]; c[j] = col[i + j]; }
        }
    }
    for (int j = 0; j < m; j++) {
        if ((unsigned)c[j] < (unsigned)n && (unsigned)r[j] < (unsigned)n) {
            int p = atomicAdd(&g_cur[c[j]], 1);
            if (p < e) g_rows[p] = r[j];
        }
    }
}

// h1s[n][f] = (x[n] . W1[:,f]) * dinv[n], stored as half2 pairs.
__global__ void k_gemm1(const float* __restrict__ x,
                        const float* __restrict__ W1, int n) {
    __shared__ __align__(16) float Ws[INF_ * HID_];   // 8 KB, [k][f]
    __shared__ float Xs[128 * 65];
    int tid = threadIdx.x;
    int fg = tid >> 6;          // 0..3  (features fg*4 .. fg*4+3)
    int q  = tid & 63;
    int base = blockIdx.x * 128;

    for (int i = tid; i < INF_ * HID_; i += 256) Ws[i] = W1[i];

    float4 a0 = {0.f, 0.f, 0.f, 0.f};
    float4 a1 = {0.f, 0.f, 0.f, 0.f};

    for (int kc = 0; kc < 2; kc++) {
        __syncthreads();
        for (int idx = tid; idx < 128 * 16; idx += 256) {
            int row = idx >> 4, c4 = idx & 15;
            int node = base + row;
            float4 v = {0.f, 0.f, 0.f, 0.f};
            if (node < n) v = *(const float4*)&x[node * INF_ + kc * 64 + c4 * 4];
            float* dst = &Xs[row * 65 + c4 * 4];
            dst[0] = v.x; dst[1] = v.y; dst[2] = v.z; dst[3] = v.w;
        }
        __syncthreads();
#pragma unroll 8
        for (int k = 0; k < 64; k++) {
            float xv0 = Xs[q * 65 + k];
            float xv1 = Xs[(q + 64) * 65 + k];
            float4 w4 = *(const float4*)&Ws[(kc * 64 + k) * HID_ + fg * 4];
            a0.x = fmaf(xv0, w4.x, a0.x); a0.y = fmaf(xv0, w4.y, a0.y);
            a0.z = fmaf(xv0, w4.z, a0.z); a0.w = fmaf(xv0, w4.w, a0.w);
            a1.x = fmaf(xv1, w4.x, a1.x); a1.y = fmaf(xv1, w4.y, a1.y);
            a1.z = fmaf(xv1, w4.z, a1.z); a1.w = fmaf(xv1, w4.w, a1.w);
        }
    }
    int n0 = base + q, n1 = base + q + 64;
    if (n0 < n) {
        float d = g_dinv[n0];
        g_h1s[n0 * 8 + fg * 2]     = __floats2half2_rn(a0.x * d, a0.y * d);
        g_h1s[n0 * 8 + fg * 2 + 1] = __floats2half2_rn(a0.z * d, a0.w * d);
    }
    if (n1 < n) {
        float d = g_dinv[n1];
        g_h1s[n1 * 8 + fg * 2]     = __floats2half2_rn(a1.x * d, a1.y * d);
        g_h1s[n1 * 8 + fg * 2 + 1] = __floats2half2_rn(a1.z * d, a1.w * d);
    }
}

// Layer-1 aggregate + relu, pre-scaled for layer 2:
// o1s[n][f] = relu(dinv*(h1s[n]+sum_r h1s[r]) + b1) * dinv
// Warp per node: 32 lanes = 4 edge-groups x 8 feature-lanes (half2 each).
__global__ void k_agg1f(const float* __restrict__ b1, int n) {
    int tid = threadIdx.x, lane = tid & 31, w = tid >> 5;
    int eg = lane >> 3, t = lane & 7;
    int node = blockIdx.x * 8 + w;
    if (node >= n) return;
    float2 s = {0.f, 0.f};
    if (eg == 0) {
        float2 self = __half22float2(g_h1s[node * 8 + t]);
        s = self;
    }
    int e0 = g_off[node], e1 = g_off[node + 1];
    for (int e = e0 + eg; e < e1; e += 4) {
        int r = __ldg(&g_rows[e]);
        float2 v = __half22float2(g_h1s[r * 8 + t]);
        s.x += v.x; s.y += v.y;
    }
    s.x += __shfl_xor_sync(0xffffffffu, s.x, 8);
    s.y += __shfl_xor_sync(0xffffffffu, s.y, 8);
    s.x += __shfl_xor_sync(0xffffffffu, s.x, 16);
    s.y += __shfl_xor_sync(0xffffffffu, s.y, 16);
    if (lane < 8) {
        float d = g_dinv[node];
        float2 bb = ((const float2*)b1)[t];
        float ox = fmaxf(fmaf(s.x, d, bb.x), 0.f) * d;
        float oy = fmaxf(fmaf(s.y, d, bb.y), 0.f) * d;
        g_o1s[node * 8 + t] = __floats2half2_rn(ox, oy);
    }
}

// Layer-2 fully fused: 16-dim aggregate (A commutes with W2), 16->64 GEMM +
// bias + relu accumulated into the global pool; last block does the epilogue.
// Tiles of 8 nodes; phase A = warp-per-node gather, phase B = 256-thread GEMM.
__global__ void k_agg2f(const float* __restrict__ b2,
                        const float* __restrict__ W2,
                        const float* __restrict__ fcW,
                        const float* __restrict__ fcb,
                        float* __restrict__ out, int n) {
    __shared__ __align__(16) float Ws[HID_ * NC_];   // 4 KB, [j][k]
    __shared__ float A16[8 * 17];
    __shared__ float red[8 * 66];
    int tid = threadIdx.x, lane = tid & 31, w = tid >> 5;
    for (int i = tid; i < HID_ * NC_; i += 256) Ws[i] = W2[i];

    int eg = lane >> 3, tA = lane & 7;       // phase-A mapping
    int wB = tid >> 5, cB = tid & 31;        // phase-B: node slot, col pair
    float2 bb = ((const float2*)b2)[cB];
    float2 acc = {0.f, 0.f};

    int ntiles = (n + 7) / 8;

    for (int tile = blockIdx.x; tile < ntiles; tile += gridDim.x) {
        __syncthreads();                     // protect A16 reuse
        int node = tile * 8 + w;
        if (node < n) {
            float2 s = {0.f, 0.f};
            if (eg == 0) s = __half22float2(g_o1s[node * 8 + tA]);
            int e0 = g_off[node], e1 = g_off[node + 1];
            for (int e = e0 + eg; e < e1; e += 4) {
                int r = __ldg(&g_rows[e]);
                float2 v = __half22float2(g_o1s[r * 8 + tA]);
                s.x += v.x; s.y += v.y;
            }
            s.x += __shfl_xor_sync(0xffffffffu, s.x, 8);
            s.y += __shfl_xor_sync(0xffffffffu, s.y, 8);
            s.x += __shfl_xor_sync(0xffffffffu, s.x, 16);
            s.y += __shfl_xor_sync(0xffffffffu, s.y, 16);
            if (lane < 8) {
                float d = g_dinv[node];
                A16[w * 17 + 2 * tA]     = s.x * d;
                A16[w * 17 + 2 * tA + 1] = s.y * d;
            }
        }
        __syncthreads();
        int node2 = tile * 8 + wB;
        if (node2 < n) {
            float2 p = bb;
#pragma unroll
            for (int j = 0; j < HID_; j++) {
                float o = A16[wB * 17 + j];
                float2 w2 = *(const float2*)&Ws[j * NC_ + 2 * cB];
                p.x = fmaf(o, w2.x, p.x);
                p.y = fmaf(o, w2.y, p.y);
            }
            acc.x += fmaxf(p.x, 0.f);
            acc.y += fmaxf(p.y, 0.f);
        }
    }

    // block-level pool reduce
    __syncthreads();
    red[wB * 66 + 2 * cB]     = acc.x;
    red[wB * 66 + 2 * cB + 1] = acc.y;
    __syncthreads();
    if (tid < 64) {
        float tot = 0.f;
#pragma unroll
        for (int i = 0; i < 8; i++) tot += red[i * 66 + tid];
        atomicAdd(&g_Sacc[tid * 64], tot);
    }

    // last block computes the epilogue
    __threadfence();
    __shared__ int amLast;
    if (tid == 0) amLast = (atomicAdd(&g_done, 1) == gridDim.x - 1);
    __syncthreads();
    if (amLast && tid == 0) {
        float nf = (float)n;
        float p0 = nf * fcb[0], p1 = nf * fcb[1];
        for (int k = 0; k < NC_; k++) {
            float sv = g_Sacc[k * 64];
            p0 = fmaf(sv, fcW[k * 2 + 0], p0);
            p1 = fmaf(sv, fcW[k * 2 + 1], p1);
        }
        float m = fmaxf(p0, p1);
        float l = m + logf(expf(p0 - m) + expf(p1 - m));
        out[0] = p0 - l;
        out[1] = p1 - l;
    }
}

// ---------------- launcher ----------------
extern "C" void kernel_launch(void* const* d_in, const int* in_sizes, int n_in,
                              void* d_out, int out_size) {
    const float* x   = (const float*)d_in[0];
    const void*  ei  = (const void*)d_in[1];
    const float* W1  = (const float*)d_in[2];
    const float* b1  = (const float*)d_in[3];
    const float* W2  = (const float*)d_in[4];
    const float* b2  = (const float*)d_in[5];
    const float* fcW = (const float*)d_in[6];
    const float* fcb = (const float*)d_in[7];
    float* out = (float*)d_out;

    int n = in_sizes[0] / INF_;   // 100000
    int e = in_sizes[1] / 2;      // 3200000
    if (n > NN) n = NN;
    if (e > EE) e = EE;

    int nbScan  = (n + 1023) / 1024;
    int nbEdge4 = (e + 1023) / 1024;

    k_init  <<<(n + 255) / 256, 256>>>((const unsigned int*)ei, n);
    k_count <<<nbEdge4, 256>>>(ei, e, n);
    k_scan_a<<<nbScan, 256>>>(n);
    k_scan_c<<<nbScan, 1024>>>(n, e);
    k_fill  <<<nbEdge4, 256>>>(ei, e, n);
    k_gemm1 <<<(n + 127) / 128, 256>>>(x, W1, n);
    k_agg1f <<<(n + 7) / 8, 256>>>(b1, n);
    k_agg2f <<<1184, 256>>>(b2, W2, fcW, fcb, out, n);
}